// round 10
// baseline (speedup 1.0000x reference)
#include <cuda_runtime.h>
#include <cstddef>
#include <cstdint>

// FusionAdjacency: Af = rownorm( sigmoid(g)*scatter(s) + (1-sigmoid(g))*scatter(t) )
//
// R9: TMA bulk-store fill. R8 profiling showed the 256MB zero-fill is
// STG.128-issue-bound (12 cyc/SMSP -> 6.2 TB/s ceiling, issue%=9 matches).
// cp.async.bulk shared->global moves 16KB per instruction, removing the
// issue bound so the fill runs at the DRAM write ceiling (~7 TB/s).
//  K1: per-block: zero 16KB smem staging buffer; elected thread issues 8x16KB
//      bulk stores to the block's 128KB slice; hist folded (<=1 edge/thread).
//  K2: finalize rowinv, re-zero rowsum (graph-replay safe).
//  K3: scatter all edges (dual independent RED chains; L2 tail-warm).

#define NN 8192
#define STAGE_BYTES 16384          // smem staging buffer
#define BLOCK_BYTES (8 * STAGE_BYTES)   // 128 KB per block
#define FILL_BLOCKS 2048           // 2048 * 128KB = 256 MB

__device__ float g_rowsum[NN];  // zero at module load; K2 re-zeros each call
__device__ float g_rowinv[NN];

__device__ __forceinline__ uint32_t smem_u32(const void* p) {
    uint32_t a;
    asm("{ .reg .u64 t; cvta.to.shared.u64 t, %1; cvt.u32.u64 %0, t; }"
        : "=r"(a) : "l"(p));
    return a;
}

// ---------------------------------------------------------------- K1
__global__ __launch_bounds__(256) void k1_fill_hist(
        const int* __restrict__ rows_s, const float* __restrict__ vals_s, int Es,
        const int* __restrict__ rows_t, const float* __restrict__ vals_t, int Et,
        const float* __restrict__ gamma, float* __restrict__ out,
        long long total_bytes) {
    __shared__ __align__(128) float4 stage[STAGE_BYTES / 16];

    const int tid = blockIdx.x * blockDim.x + threadIdx.x;
    const int stride = gridDim.x * blockDim.x;

    // zero the staging buffer (16KB / 256 threads = 4 float4 each)
    const float4 z = make_float4(0.f, 0.f, 0.f, 0.f);
#pragma unroll
    for (int i = 0; i < 4; i++) stage[threadIdx.x + i * 256] = z;
    __syncthreads();
    // order generic-proxy smem writes before async-proxy (TMA) reads
    asm volatile("fence.proxy.async.shared::cta;" ::: "memory");

    // elected thread issues this block's bulk stores (async; drain in bg)
    if (threadIdx.x == 0) {
        const uint32_t saddr = smem_u32(stage);
        long long base = (long long)blockIdx.x * BLOCK_BYTES;
        char* gbase = reinterpret_cast<char*>(out) + base;
#pragma unroll
        for (int j = 0; j < 8; j++) {
            long long off = base + (long long)j * STAGE_BYTES;
            if (off < total_bytes) {
                uint32_t nb = (uint32_t)((total_bytes - off < STAGE_BYTES)
                                         ? (total_bytes - off) : STAGE_BYTES);
                asm volatile(
                    "cp.async.bulk.global.shared::cta.bulk_group [%0], [%1], %2;"
                    :: "l"(gbase + (long long)j * STAGE_BYTES), "r"(saddr), "r"(nb)
                    : "memory");
            }
        }
        asm volatile("cp.async.bulk.commit_group;" ::: "memory");
    }

    // hist fold: <=1 edge per thread per list, fire-and-forget REDs;
    // overlaps the TMA drain
    const float g = gamma[0];
    const float alpha = 1.0f / (1.0f + expf(-g));
    const float beta = 1.0f - alpha;
    for (int e = tid; e < Es; e += stride)
        atomicAdd(&g_rowsum[__ldg(&rows_s[e])], alpha * __ldg(&vals_s[e]));
    for (int e = tid; e < Et; e += stride)
        atomicAdd(&g_rowsum[__ldg(&rows_t[e])], beta * __ldg(&vals_t[e]));

    // ensure bulk stores are complete before the block retires
    if (threadIdx.x == 0) {
        asm volatile("cp.async.bulk.wait_group 0;" ::: "memory");
    }
    __syncthreads();
}

// ---------------------------------------------------------------- K2
__global__ void k2_finalize() {
    int i = blockIdx.x * blockDim.x + threadIdx.x;
    if (i < NN) {
        float s = g_rowsum[i];
        g_rowinv[i] = (s == 0.0f) ? 1.0f : (1.0f / s);
        g_rowsum[i] = 0.0f;   // ready for next graph replay
    }
}

// ---------------------------------------------------------------- K3
__global__ __launch_bounds__(256) void k3_scatter(
        const int* __restrict__ rows_s, const int* __restrict__ cols_s,
        const float* __restrict__ vals_s, int Es,
        const int* __restrict__ rows_t, const int* __restrict__ cols_t,
        const float* __restrict__ vals_t, int Et,
        const float* __restrict__ gamma, float* __restrict__ out) {
    const float g = gamma[0];
    const float alpha = 1.0f / (1.0f + expf(-g));
    const float beta = 1.0f - alpha;
    const int tid = blockIdx.x * blockDim.x + threadIdx.x;
    const int stride = gridDim.x * blockDim.x;

    const int n = (Es > Et) ? Es : Et;
    for (int e = tid; e < n; e += stride) {
        int rs = 0, cs = 0;  float vs = 0.0f;
        if (e < Es) {
            rs = __ldg(&rows_s[e]);
            cs = __ldg(&cols_s[e]);
            vs = __ldg(&vals_s[e]);
        }
        int rt = 0, ct = 0;  float vt = 0.0f;
        if (e < Et) {
            rt = __ldg(&rows_t[e]);
            ct = __ldg(&cols_t[e]);
            vt = __ldg(&vals_t[e]);
        }
        float invs = g_rowinv[rs];
        float invt = g_rowinv[rt];
        if (e < Es) atomicAdd(&out[((size_t)rs << 13) + cs], alpha * vs * invs);
        if (e < Et) atomicAdd(&out[((size_t)rt << 13) + ct], beta * vt * invt);
    }
}

// ---------------------------------------------------------------- launch
extern "C" void kernel_launch(void* const* d_in, const int* in_sizes, int n_in,
                              void* d_out, int out_size) {
    const int*   rows_s = (const int*)d_in[0];
    const int*   cols_s = (const int*)d_in[1];
    const float* vals_s = (const float*)d_in[2];
    const int*   rows_t = (const int*)d_in[3];
    const int*   cols_t = (const int*)d_in[4];
    const float* vals_t = (const float*)d_in[5];
    const float* gamma  = (const float*)d_in[6];
    float* out = (float*)d_out;

    const int Es = in_sizes[0];
    const int Et = in_sizes[3];
    const long long total_bytes = (long long)out_size * sizeof(float);
    // blocks needed to cover the output at 128KB each
    const int fillB = (int)((total_bytes + BLOCK_BYTES - 1) / BLOCK_BYTES);

    k1_fill_hist<<<fillB, 256>>>(rows_s, vals_s, Es, rows_t, vals_t, Et,
                                 gamma, out, total_bytes);

    k2_finalize<<<(NN + 255) / 256, 256>>>();

    k3_scatter<<<1024, 256>>>(rows_s, cols_s, vals_s, Es,
                              rows_t, cols_t, vals_t, Et, gamma, out);
}

// round 11
// speedup vs baseline: 1.0020x; 1.0020x over previous
#include <cuda_runtime.h>
#include <cstddef>
#include <cstdint>

// FusionAdjacency: Af = rownorm( sigmoid(g)*scatter(s) + (1-sigmoid(g))*scatter(t) )
//
// R9: TMA bulk-store fill. R8 profiling showed the 256MB zero-fill is
// STG.128-issue-bound (12 cyc/SMSP -> 6.2 TB/s ceiling, issue%=9 matches).
// cp.async.bulk shared->global moves 16KB per instruction, removing the
// issue bound so the fill runs at the DRAM write ceiling (~7 TB/s).
//  K1: per-block: zero 16KB smem staging buffer; elected thread issues 8x16KB
//      bulk stores to the block's 128KB slice; hist folded (<=1 edge/thread).
//  K2: finalize rowinv, re-zero rowsum (graph-replay safe).
//  K3: scatter all edges (dual independent RED chains; L2 tail-warm).

#define NN 8192
#define STAGE_BYTES 16384          // smem staging buffer
#define BLOCK_BYTES (8 * STAGE_BYTES)   // 128 KB per block
#define FILL_BLOCKS 2048           // 2048 * 128KB = 256 MB

__device__ float g_rowsum[NN];  // zero at module load; K2 re-zeros each call
__device__ float g_rowinv[NN];

__device__ __forceinline__ uint32_t smem_u32(const void* p) {
    uint32_t a;
    asm("{ .reg .u64 t; cvta.to.shared.u64 t, %1; cvt.u32.u64 %0, t; }"
        : "=r"(a) : "l"(p));
    return a;
}

// ---------------------------------------------------------------- K1
__global__ __launch_bounds__(256) void k1_fill_hist(
        const int* __restrict__ rows_s, const float* __restrict__ vals_s, int Es,
        const int* __restrict__ rows_t, const float* __restrict__ vals_t, int Et,
        const float* __restrict__ gamma, float* __restrict__ out,
        long long total_bytes) {
    __shared__ __align__(128) float4 stage[STAGE_BYTES / 16];

    const int tid = blockIdx.x * blockDim.x + threadIdx.x;
    const int stride = gridDim.x * blockDim.x;

    // zero the staging buffer (16KB / 256 threads = 4 float4 each)
    const float4 z = make_float4(0.f, 0.f, 0.f, 0.f);
#pragma unroll
    for (int i = 0; i < 4; i++) stage[threadIdx.x + i * 256] = z;
    __syncthreads();
    // order generic-proxy smem writes before async-proxy (TMA) reads
    asm volatile("fence.proxy.async.shared::cta;" ::: "memory");

    // elected thread issues this block's bulk stores (async; drain in bg)
    if (threadIdx.x == 0) {
        const uint32_t saddr = smem_u32(stage);
        long long base = (long long)blockIdx.x * BLOCK_BYTES;
        char* gbase = reinterpret_cast<char*>(out) + base;
#pragma unroll
        for (int j = 0; j < 8; j++) {
            long long off = base + (long long)j * STAGE_BYTES;
            if (off < total_bytes) {
                uint32_t nb = (uint32_t)((total_bytes - off < STAGE_BYTES)
                                         ? (total_bytes - off) : STAGE_BYTES);
                asm volatile(
                    "cp.async.bulk.global.shared::cta.bulk_group [%0], [%1], %2;"
                    :: "l"(gbase + (long long)j * STAGE_BYTES), "r"(saddr), "r"(nb)
                    : "memory");
            }
        }
        asm volatile("cp.async.bulk.commit_group;" ::: "memory");
    }

    // hist fold: <=1 edge per thread per list, fire-and-forget REDs;
    // overlaps the TMA drain
    const float g = gamma[0];
    const float alpha = 1.0f / (1.0f + expf(-g));
    const float beta = 1.0f - alpha;
    for (int e = tid; e < Es; e += stride)
        atomicAdd(&g_rowsum[__ldg(&rows_s[e])], alpha * __ldg(&vals_s[e]));
    for (int e = tid; e < Et; e += stride)
        atomicAdd(&g_rowsum[__ldg(&rows_t[e])], beta * __ldg(&vals_t[e]));

    // ensure bulk stores are complete before the block retires
    if (threadIdx.x == 0) {
        asm volatile("cp.async.bulk.wait_group 0;" ::: "memory");
    }
    __syncthreads();
}

// ---------------------------------------------------------------- K2
__global__ void k2_finalize() {
    int i = blockIdx.x * blockDim.x + threadIdx.x;
    if (i < NN) {
        float s = g_rowsum[i];
        g_rowinv[i] = (s == 0.0f) ? 1.0f : (1.0f / s);
        g_rowsum[i] = 0.0f;   // ready for next graph replay
    }
}

// ---------------------------------------------------------------- K3
__global__ __launch_bounds__(256) void k3_scatter(
        const int* __restrict__ rows_s, const int* __restrict__ cols_s,
        const float* __restrict__ vals_s, int Es,
        const int* __restrict__ rows_t, const int* __restrict__ cols_t,
        const float* __restrict__ vals_t, int Et,
        const float* __restrict__ gamma, float* __restrict__ out) {
    const float g = gamma[0];
    const float alpha = 1.0f / (1.0f + expf(-g));
    const float beta = 1.0f - alpha;
    const int tid = blockIdx.x * blockDim.x + threadIdx.x;
    const int stride = gridDim.x * blockDim.x;

    const int n = (Es > Et) ? Es : Et;
    for (int e = tid; e < n; e += stride) {
        int rs = 0, cs = 0;  float vs = 0.0f;
        if (e < Es) {
            rs = __ldg(&rows_s[e]);
            cs = __ldg(&cols_s[e]);
            vs = __ldg(&vals_s[e]);
        }
        int rt = 0, ct = 0;  float vt = 0.0f;
        if (e < Et) {
            rt = __ldg(&rows_t[e]);
            ct = __ldg(&cols_t[e]);
            vt = __ldg(&vals_t[e]);
        }
        float invs = g_rowinv[rs];
        float invt = g_rowinv[rt];
        if (e < Es) atomicAdd(&out[((size_t)rs << 13) + cs], alpha * vs * invs);
        if (e < Et) atomicAdd(&out[((size_t)rt << 13) + ct], beta * vt * invt);
    }
}

// ---------------------------------------------------------------- launch
extern "C" void kernel_launch(void* const* d_in, const int* in_sizes, int n_in,
                              void* d_out, int out_size) {
    const int*   rows_s = (const int*)d_in[0];
    const int*   cols_s = (const int*)d_in[1];
    const float* vals_s = (const float*)d_in[2];
    const int*   rows_t = (const int*)d_in[3];
    const int*   cols_t = (const int*)d_in[4];
    const float* vals_t = (const float*)d_in[5];
    const float* gamma  = (const float*)d_in[6];
    float* out = (float*)d_out;

    const int Es = in_sizes[0];
    const int Et = in_sizes[3];
    const long long total_bytes = (long long)out_size * sizeof(float);
    // blocks needed to cover the output at 128KB each
    const int fillB = (int)((total_bytes + BLOCK_BYTES - 1) / BLOCK_BYTES);

    k1_fill_hist<<<fillB, 256>>>(rows_s, vals_s, Es, rows_t, vals_t, Et,
                                 gamma, out, total_bytes);

    k2_finalize<<<(NN + 255) / 256, 256>>>();

    k3_scatter<<<1024, 256>>>(rows_s, cols_s, vals_s, Es,
                              rows_t, cols_t, vals_t, Et, gamma, out);
}